// round 2
// baseline (speedup 1.0000x reference)
#include <cuda_runtime.h>
#include <math.h>

#define NROWS 500000
#define DIN   256
#define DHID  128
#define NHEAD 4
#define HBLK  32      // DHID / NHEAD
#define DOUT  4
#define TM    128     // rows per CTA
#define KC    16      // k-chunk

// ---------------- scratch (static device allocs are allowed) ----------------
__device__ int g_cnt[NHEAD];
__device__ int g_idx[NHEAD][NROWS];

// ---------------- helpers: packed f32x2 ----------------
__device__ __forceinline__ unsigned long long pack2(float v) {
    unsigned long long r;
    unsigned int b = __float_as_uint(v);
    asm("mov.b64 %0, {%1, %1};" : "=l"(r) : "r"(b));
    return r;
}
__device__ __forceinline__ void fma2(unsigned long long& acc,
                                     unsigned long long a,
                                     unsigned long long b) {
    asm("fma.rn.f32x2 %0, %1, %2, %0;" : "+l"(acc) : "l"(a), "l"(b));
}
__device__ __forceinline__ void unpack2(unsigned long long v, float& lo, float& hi) {
    unsigned int ulo, uhi;
    asm("mov.b64 {%0, %1}, %2;" : "=r"(ulo), "=r"(uhi) : "l"(v));
    lo = __uint_as_float(ulo);
    hi = __uint_as_float(uhi);
}

// ---------------- kernel 1: zero counters ----------------
__global__ void zero_kernel() {
    if (threadIdx.x < NHEAD) g_cnt[threadIdx.x] = 0;
}

// ---------------- kernel 2: bucket rows by head ----------------
__global__ void scatter_kernel(const int* __restrict__ heads, int n) {
    __shared__ int s_cnt[NHEAD];
    __shared__ int s_base[NHEAD];
    int t = blockIdx.x * blockDim.x + threadIdx.x;
    if (threadIdx.x < NHEAD) s_cnt[threadIdx.x] = 0;
    __syncthreads();
    int h = 0, rank = 0;
    bool valid = (t < n);
    if (valid) {
        h = heads[t];
        rank = atomicAdd(&s_cnt[h], 1);
    }
    __syncthreads();
    if (threadIdx.x < NHEAD)
        s_base[threadIdx.x] = atomicAdd(&g_cnt[threadIdx.x], s_cnt[threadIdx.x]);
    __syncthreads();
    if (valid) g_idx[h][s_base[h] + rank] = t;
}

// ---------------- kernel 3: bucketed fused GEMM ----------------
// CTA: 128 rows (one head bucket) x 32 hidden cols. 128 threads.
// thread tile: 8 rows (4 f32x2 pairs) x 4 cols -> 16 FFMA2 / k.
__global__ void __launch_bounds__(128)
gemm_kernel(const float* __restrict__ x,
            const float* __restrict__ W1,
            const float* __restrict__ W2,
            float* __restrict__ out) {
    __shared__ float w1s[DIN][HBLK];        // 32 KB : head block of W1
    __shared__ float xs[KC][TM];            //  8 KB : transposed x chunk
    __shared__ float w2s[HBLK * DOUT];      // 512 B : scaled W2 block
    __shared__ float s_out[TM][DOUT];       //  2 KB : output reduction

    const int hd    = blockIdx.y;
    const int cnt   = g_cnt[hd];
    const int start = blockIdx.x * TM;
    if (start >= cnt) return;

    const int tid = threadIdx.x;
    const int tc  = tid & 7;    // col group 0..7 (4 cols each)
    const int tr  = tid >> 3;   // row group 0..15 (8 rows each)

    // ---- load W1 head block (coalesced: each warp covers one 128B k-row) ----
    #pragma unroll
    for (int i = 0; i < (DIN * HBLK) / 128; ++i) {
        int f = tid + i * 128;
        int k = f >> 5, j = f & 31;
        w1s[k][j] = W1[k * DHID + hd * HBLK + j];
    }
    // ---- W2 block, fold 1/sqrt(128) ----
    {
        int j = tid >> 2, d = tid & 3;
        w2s[tid] = W2[(hd * HBLK + j) * DOUT + d] * 0.08838834764831845f;
    }
    // ---- zero reduction buffer ----
    #pragma unroll
    for (int d = 0; d < DOUT; ++d) s_out[tid][d] = 0.f;

    // ---- this thread loads one gathered row ----
    const bool rvalid = (start + tid) < cnt;
    const int  ridx   = rvalid ? g_idx[hd][start + tid] : 0;
    const float* xr   = x + (size_t)ridx * DIN;

    unsigned long long acc[4][4];
    #pragma unroll
    for (int m = 0; m < 4; ++m)
        #pragma unroll
        for (int c = 0; c < 4; ++c) acc[m][c] = 0ull;

    // prologue: stage chunk 0
    float4 st[KC / 4];
    #pragma unroll
    for (int i = 0; i < KC / 4; ++i)
        st[i] = rvalid ? *(const float4*)(xr + i * 4) : make_float4(0.f, 0.f, 0.f, 0.f);

    #pragma unroll 1
    for (int ch = 0; ch < DIN / KC; ++ch) {
        // store staged chunk transposed (bank = tid%32 per thread -> conflict-free)
        #pragma unroll
        for (int i = 0; i < KC / 4; ++i) {
            xs[i * 4 + 0][tid] = st[i].x;
            xs[i * 4 + 1][tid] = st[i].y;
            xs[i * 4 + 2][tid] = st[i].z;
            xs[i * 4 + 3][tid] = st[i].w;
        }
        __syncthreads();

        // prefetch next chunk into registers (overlaps with compute below)
        if (ch + 1 < DIN / KC) {
            const float* p = xr + (ch + 1) * KC;
            #pragma unroll
            for (int i = 0; i < KC / 4; ++i)
                st[i] = rvalid ? *(const float4*)(p + i * 4) : make_float4(0.f, 0.f, 0.f, 0.f);
        }

        const int kbase = ch * KC;
        #pragma unroll
        for (int k = 0; k < KC; ++k) {
            ulonglong2 xa = *(const ulonglong2*)&xs[k][tr * 8];
            ulonglong2 xb = *(const ulonglong2*)&xs[k][tr * 8 + 4];
            float4 wv = *(const float4*)&w1s[kbase + k][tc * 4];
            unsigned long long xp[4] = { xa.x, xa.y, xb.x, xb.y };
            unsigned long long wp[4] = { pack2(wv.x), pack2(wv.y), pack2(wv.z), pack2(wv.w) };
            #pragma unroll
            for (int m = 0; m < 4; ++m)
                #pragma unroll
                for (int c = 0; c < 4; ++c)
                    fma2(acc[m][c], xp[m], wp[c]);
        }
        __syncthreads();
    }

    // ---- epilogue: scale, silu, multiply by W2 block -> per-thread partials ----
    float po[8][DOUT];
    #pragma unroll
    for (int r = 0; r < 8; ++r)
        #pragma unroll
        for (int d = 0; d < DOUT; ++d) po[r][d] = 0.f;

    #pragma unroll
    for (int m = 0; m < 4; ++m) {
        #pragma unroll
        for (int c = 0; c < 4; ++c) {
            float lo, hi;
            unpack2(acc[m][c], lo, hi);
            lo *= 0.0625f;   // 1/sqrt(256)
            hi *= 0.0625f;
            float slo = lo / (1.f + __expf(-lo));
            float shi = hi / (1.f + __expf(-hi));
            const float4 w2v = *(const float4*)&w2s[(tc * 4 + c) * 4];
            po[2 * m][0] += slo * w2v.x;  po[2 * m][1] += slo * w2v.y;
            po[2 * m][2] += slo * w2v.z;  po[2 * m][3] += slo * w2v.w;
            po[2 * m + 1][0] += shi * w2v.x;  po[2 * m + 1][1] += shi * w2v.y;
            po[2 * m + 1][2] += shi * w2v.z;  po[2 * m + 1][3] += shi * w2v.w;
        }
    }

    // ---- deterministic staged reduction over the 8 col-groups ----
    #pragma unroll 1
    for (int g = 0; g < 8; ++g) {
        if (tc == g) {
            #pragma unroll
            for (int r = 0; r < 8; ++r) {
                int row = tr * 8 + r;
                #pragma unroll
                for (int d = 0; d < DOUT; ++d) s_out[row][d] += po[r][d];
            }
        }
        __syncthreads();
    }

    // ---- scattered float4 store to original row positions ----
    if (rvalid) {
        float4 o = make_float4(s_out[tid][0], s_out[tid][1], s_out[tid][2], s_out[tid][3]);
        *(float4*)(out + (size_t)ridx * DOUT) = o;
    }
}

// ---------------- launch ----------------
extern "C" void kernel_launch(void* const* d_in, const int* in_sizes, int n_in,
                              void* d_out, int out_size) {
    const float* x     = (const float*)d_in[0];
    const float* W1    = (const float*)d_in[1];
    const float* W2    = (const float*)d_in[2];
    const int*   heads = (const int*)d_in[3];
    int n = in_sizes[3];

    zero_kernel<<<1, 32>>>();
    scatter_kernel<<<(n + 255) / 256, 256>>>(heads, n);

    int nt = (n + TM - 1) / TM;
    dim3 grid(nt, NHEAD);
    gemm_kernel<<<grid, 128>>>(x, W1, W2, (float*)d_out);
}

// round 4
// speedup vs baseline: 1.6623x; 1.6623x over previous
#include <cuda_runtime.h>
#include <math.h>

#define NROWS 500000
#define DIN   256
#define DHID  128
#define NHEAD 4
#define HBLK  32      // DHID / NHEAD
#define DOUT  4
#define TM    128     // rows per CTA
#define KC    32      // k-chunk (128 B per row)
#define NCH   (DIN / KC)   // 8

// ---------------- scratch ----------------
__device__ int g_cnt[NHEAD];
__device__ int g_idx[NHEAD][NROWS];

// ---------------- packed f32x2 helpers ----------------
__device__ __forceinline__ unsigned long long pack2(float v) {
    unsigned long long r;
    unsigned int b = __float_as_uint(v);
    asm("mov.b64 %0, {%1, %1};" : "=l"(r) : "r"(b));
    return r;
}
__device__ __forceinline__ void fma2(unsigned long long& acc,
                                     unsigned long long a,
                                     unsigned long long b) {
    asm("fma.rn.f32x2 %0, %1, %2, %0;" : "+l"(acc) : "l"(a), "l"(b));
}
__device__ __forceinline__ void unpack2(unsigned long long v, float& lo, float& hi) {
    unsigned int ulo, uhi;
    asm("mov.b64 {%0, %1}, %2;" : "=r"(ulo), "=r"(uhi) : "l"(v));
    lo = __uint_as_float(ulo);
    hi = __uint_as_float(uhi);
}

// ---------------- kernel 1: zero counters ----------------
__global__ void zero_kernel() {
    if (threadIdx.x < NHEAD) g_cnt[threadIdx.x] = 0;
}

// ---------------- kernel 2: bucket rows by head ----------------
__global__ void scatter_kernel(const int* __restrict__ heads, int n) {
    __shared__ int s_cnt[NHEAD];
    __shared__ int s_base[NHEAD];
    int t = blockIdx.x * blockDim.x + threadIdx.x;
    if (threadIdx.x < NHEAD) s_cnt[threadIdx.x] = 0;
    __syncthreads();
    int h = 0, rank = 0;
    bool valid = (t < n);
    if (valid) {
        h = heads[t];
        rank = atomicAdd(&s_cnt[h], 1);
    }
    __syncthreads();
    if (threadIdx.x < NHEAD)
        s_base[threadIdx.x] = atomicAdd(&g_cnt[threadIdx.x], s_cnt[threadIdx.x]);
    __syncthreads();
    if (valid) g_idx[h][s_base[h] + rank] = t;
}

// ---------------- kernel 3: bucketed fused GEMM ----------------
// CTA: 128 gathered rows x 32 hidden cols, 128 threads.
// Cooperative coalesced gather (nL=4 per LDG.128), XOR-swizzled k-major x tile,
// thread tile 8 rows x 4 cols as f32x2 row-pairs (16 FFMA2 per k).
__global__ void __launch_bounds__(128, 4)
gemm_kernel(const float* __restrict__ x,
            const float* __restrict__ W1,
            const float* __restrict__ W2,
            float* __restrict__ out) {
    extern __shared__ float sm[];
    float* w1s   = sm;                         // [256][32]  (32 KB)
    float* xs    = sm + DIN * HBLK;            // [32][128]  (16 KB, swizzled)
    float* s_out = sm + DIN * HBLK + KC * TM;  // [128][4]   (2 KB)

    const int hd    = blockIdx.y;
    const int cnt   = g_cnt[hd];
    const int start = blockIdx.x * TM;
    if (start >= cnt) return;

    const int tid = threadIdx.x;
    const int tc  = tid & 7;    // col group 0..7 (4 cols each) / load col-chunk
    const int tr  = tid >> 3;   // row group 0..15 (8 rows each) / load row base

    // ---- load W1 head block (float4 coalesced: flat f4 idx = k*8 + j4) ----
    #pragma unroll
    for (int i = 0; i < (DIN * HBLK) / (128 * 4); ++i) {   // 16 iters
        int f = tid + i * 128;
        int k = f >> 3, j4 = f & 7;
        ((float4*)w1s)[f] = *(const float4*)&W1[k * DHID + hd * HBLK + j4 * 4];
    }

    // ---- zero output-reduction buffer ----
    ((float4*)s_out)[tid] = make_float4(0.f, 0.f, 0.f, 0.f);

    // ---- gather pointers for this thread's 8 cooperative-load rows ----
    // pass i: row = tr + 16*i, lanes cover one full 128B line per gathered row
    const float* xp[8];
    #pragma unroll
    for (int i = 0; i < 8; ++i) {
        int r = start + tr + 16 * i;
        r = (r < cnt) ? r : (cnt - 1);                 // clamp (dup load harmless)
        xp[i] = x + (size_t)g_idx[hd][r] * DIN + tc * 4;
    }
    // this thread's own output row
    const bool rvalid = (start + tid) < cnt;
    const int  ridx   = rvalid ? g_idx[hd][start + tid] : 0;

    // ---- precomputed swizzled x-read base pointers (f&24 variants) ----
    const float* xrow[4];
    #pragma unroll
    for (int j = 0; j < 4; ++j) xrow[j] = xs + ((tr * 8) ^ (8 * j));
    const float* wcol = w1s + tc * 4;

    unsigned long long acc[4][4];
    #pragma unroll
    for (int m = 0; m < 4; ++m)
        #pragma unroll
        for (int c = 0; c < 4; ++c) acc[m][c] = 0ull;

    // prologue: stage chunk 0
    float4 st[8];
    #pragma unroll
    for (int i = 0; i < 8; ++i) st[i] = *(const float4*)(xp[i]);

    #pragma unroll 1
    for (int ch = 0; ch < NCH; ++ch) {
        // ---- store staged chunk, swizzled: phys_col = row ^ (4*tc) ----
        // (k = tc*4+j -> f(k) = 4*(k>>2) = 4*tc; conflict-free STS.32)
        #pragma unroll
        for (int i = 0; i < 8; ++i) {
            int row = tr + 16 * i;
            int p   = row ^ (4 * tc);
            xs[(tc * 4 + 0) * TM + p] = st[i].x;
            xs[(tc * 4 + 1) * TM + p] = st[i].y;
            xs[(tc * 4 + 2) * TM + p] = st[i].z;
            xs[(tc * 4 + 3) * TM + p] = st[i].w;
        }
        __syncthreads();

        // ---- prefetch next chunk (overlaps compute) ----
        if (ch + 1 < NCH) {
            #pragma unroll
            for (int i = 0; i < 8; ++i)
                st[i] = *(const float4*)(xp[i] + (ch + 1) * KC);
        }

        const float* wk = wcol + ch * KC * HBLK;
        #pragma unroll
        for (int k = 0; k < KC; ++k) {
            // swizzle: f = k&28; sel = (k>>3)&3 picks f&24 variant; (k&4) = f&4
            const float* xb = xrow[(k >> 3) & 3] + k * TM;
            ulonglong2 xa = *(const ulonglong2*)(xb + (k & 4));          // rows tr*8+0..3
            ulonglong2 xv = *(const ulonglong2*)(xb + ((k & 4) ^ 4));    // rows tr*8+4..7
            float4 wv = *(const float4*)(wk + k * HBLK);
            unsigned long long xq[4] = { xa.x, xa.y, xv.x, xv.y };
            unsigned long long w0 = pack2(wv.x), w1 = pack2(wv.y),
                               w2 = pack2(wv.z), w3 = pack2(wv.w);
            #pragma unroll
            for (int m = 0; m < 4; ++m) {
                fma2(acc[m][0], xq[m], w0);
                fma2(acc[m][1], xq[m], w1);
                fma2(acc[m][2], xq[m], w2);
                fma2(acc[m][3], xq[m], w3);
            }
        }
        __syncthreads();
    }

    // ---- epilogue: scale, silu, W2 (from gmem, scale folded) ----
    float4 w2v[4];
    #pragma unroll
    for (int c = 0; c < 4; ++c) {
        float4 t = *(const float4*)&W2[(hd * HBLK + tc * 4 + c) * DOUT];
        w2v[c] = make_float4(t.x * 0.08838834764831845f, t.y * 0.08838834764831845f,
                             t.z * 0.08838834764831845f, t.w * 0.08838834764831845f);
    }

    float po[8][DOUT];
    #pragma unroll
    for (int r = 0; r < 8; ++r)
        #pragma unroll
        for (int d = 0; d < DOUT; ++d) po[r][d] = 0.f;

    #pragma unroll
    for (int m = 0; m < 4; ++m) {
        #pragma unroll
        for (int c = 0; c < 4; ++c) {
            float lo, hi;
            unpack2(acc[m][c], lo, hi);
            lo *= 0.0625f;   // 1/sqrt(256)
            hi *= 0.0625f;
            float slo = lo / (1.f + __expf(-lo));
            float shi = hi / (1.f + __expf(-hi));
            po[2 * m][0]     += slo * w2v[c].x;  po[2 * m][1]     += slo * w2v[c].y;
            po[2 * m][2]     += slo * w2v[c].z;  po[2 * m][3]     += slo * w2v[c].w;
            po[2 * m + 1][0] += shi * w2v[c].x;  po[2 * m + 1][1] += shi * w2v[c].y;
            po[2 * m + 1][2] += shi * w2v[c].z;  po[2 * m + 1][3] += shi * w2v[c].w;
        }
    }

    // ---- deterministic staged reduction over the 8 col-groups ----
    #pragma unroll 1
    for (int g = 0; g < 8; ++g) {
        if (tc == g) {
            #pragma unroll
            for (int r = 0; r < 8; ++r) {
                int row = tr * 8 + r;
                #pragma unroll
                for (int d = 0; d < DOUT; ++d) s_out[row * DOUT + d] += po[r][d];
            }
        }
        __syncthreads();
    }

    // ---- scattered float4 store ----
    if (rvalid) {
        float4 o = *(const float4*)&s_out[tid * DOUT];
        *(float4*)(out + (size_t)ridx * DOUT) = o;
    }
}

// ---------------- launch ----------------
extern "C" void kernel_launch(void* const* d_in, const int* in_sizes, int n_in,
                              void* d_out, int out_size) {
    const float* x     = (const float*)d_in[0];
    const float* W1    = (const float*)d_in[1];
    const float* W2    = (const float*)d_in[2];
    const int*   heads = (const int*)d_in[3];
    int n = in_sizes[3];

    const int smem_bytes = (DIN * HBLK + KC * TM + TM * DOUT) * sizeof(float); // 50 KB
    static int attr_done = 0;
    if (!attr_done) {
        cudaFuncSetAttribute(gemm_kernel,
                             cudaFuncAttributeMaxDynamicSharedMemorySize, smem_bytes);
        attr_done = 1;
    }

    zero_kernel<<<1, 32>>>();
    scatter_kernel<<<(n + 255) / 256, 256>>>(heads, n);

    int nt = (n + TM - 1) / TM;
    dim3 grid(nt, NHEAD);
    gemm_kernel<<<grid, 128, smem_bytes>>>(x, W1, W2, (float*)d_out);
}

// round 5
// speedup vs baseline: 1.9255x; 1.1584x over previous
#include <cuda_runtime.h>
#include <math.h>

#define NROWS 500000
#define DIN   256
#define DHID  128
#define NHEAD 4
#define HBLK  32      // DHID / NHEAD
#define DOUT  4
#define TM    128     // rows per CTA
#define KC    32      // k-chunk (128 B per row)
#define NCH   (DIN / KC)   // 8

// ---------------- scratch ----------------
__device__ int g_cnt[NHEAD];
__device__ int g_idx[NHEAD][NROWS];

// ---------------- packed f32x2 helpers ----------------
__device__ __forceinline__ unsigned long long pack2(float v) {
    unsigned long long r;
    unsigned int b = __float_as_uint(v);
    asm("mov.b64 %0, {%1, %1};" : "=l"(r) : "r"(b));
    return r;
}
__device__ __forceinline__ void fma2(unsigned long long& acc,
                                     unsigned long long a,
                                     unsigned long long b) {
    asm("fma.rn.f32x2 %0, %1, %2, %0;" : "+l"(acc) : "l"(a), "l"(b));
}
__device__ __forceinline__ void unpack2(unsigned long long v, float& lo, float& hi) {
    unsigned int ulo, uhi;
    asm("mov.b64 {%0, %1}, %2;" : "=r"(ulo), "=r"(uhi) : "l"(v));
    lo = __uint_as_float(ulo);
    hi = __uint_as_float(uhi);
}

// ---------------- kernel 1: zero counters ----------------
__global__ void zero_kernel() {
    if (threadIdx.x < NHEAD) g_cnt[threadIdx.x] = 0;
}

// ---------------- kernel 2: bucket rows by head ----------------
__global__ void scatter_kernel(const int* __restrict__ heads, int n) {
    __shared__ int s_cnt[NHEAD];
    __shared__ int s_base[NHEAD];
    int t = blockIdx.x * blockDim.x + threadIdx.x;
    if (threadIdx.x < NHEAD) s_cnt[threadIdx.x] = 0;
    __syncthreads();
    int h = 0, rank = 0;
    bool valid = (t < n);
    if (valid) {
        h = heads[t];
        rank = atomicAdd(&s_cnt[h], 1);
    }
    __syncthreads();
    if (threadIdx.x < NHEAD)
        s_base[threadIdx.x] = atomicAdd(&g_cnt[threadIdx.x], s_cnt[threadIdx.x]);
    __syncthreads();
    if (valid) g_idx[h][s_base[h] + rank] = t;
}

// ---------------- kernel 3: bucketed fused GEMM ----------------
// Flat 1D grid: CTA resolves its (head, tile) from g_cnt. 128 gathered rows x
// 32 hidden cols per CTA, 128 threads, thread tile 8 rows x 4 cols (16 FFMA2/k).
// Coalesced cooperative gather (nL=4), XOR-swizzled k-major x tile, shuffle
// epilogue (no smem reduction).
__global__ void __launch_bounds__(128, 3)
gemm_kernel(const float* __restrict__ x,
            const float* __restrict__ W1,
            const float* __restrict__ W2,
            float* __restrict__ out) {
    __shared__ float w1s[DIN * HBLK];   // 32 KB (pre-scaled by 1/sqrt(256))
    __shared__ float xs[KC * TM];       // 16 KB (swizzled)

    // ---- resolve (head, tile) from bucket counts ----
    const int c0 = g_cnt[0], c1 = g_cnt[1], c2 = g_cnt[2], c3 = g_cnt[3];
    const int t0 = (c0 + TM - 1) >> 7, t1 = (c1 + TM - 1) >> 7,
              t2 = (c2 + TM - 1) >> 7, t3 = (c3 + TM - 1) >> 7;
    int b = blockIdx.x;
    int hd, cnt;
    if (b < t0)                     { hd = 0; cnt = c0; }
    else if ((b -= t0) < t1)        { hd = 1; cnt = c1; }
    else if ((b -= t1) < t2)        { hd = 2; cnt = c2; }
    else if ((b -= t2) < t3)        { hd = 3; cnt = c3; }
    else return;
    const int start = b << 7;

    const int tid = threadIdx.x;
    const int tc  = tid & 7;    // col group 0..7 (4 cols each)
    const int tr  = tid >> 3;   // row group 0..15 (8 rows each)

    // ---- load W1 head block, fold 1/sqrt(256) ----
    #pragma unroll
    for (int i = 0; i < (DIN * HBLK) / (128 * 4); ++i) {   // 16 iters
        int f = tid + i * 128;
        int k = f >> 3, j4 = f & 7;
        float4 t = *(const float4*)&W1[k * DHID + hd * HBLK + j4 * 4];
        ((float4*)w1s)[f] = make_float4(t.x * 0.0625f, t.y * 0.0625f,
                                        t.z * 0.0625f, t.w * 0.0625f);
    }

    // ---- gather byte-offsets for this thread's 8 cooperative-load rows ----
    const char* xB = (const char*)x;
    unsigned int xoffb[8];
    #pragma unroll
    for (int i = 0; i < 8; ++i) {
        int r = start + tr + 16 * i;
        r = (r < cnt) ? r : (cnt - 1);                 // clamp (dup load harmless)
        xoffb[i] = (unsigned int)g_idx[hd][r] * (DIN * 4) + tc * 16;
    }

    // ---- swizzled x-read float offsets (f&24 variants) ----
    int xoff[4];
    #pragma unroll
    for (int j = 0; j < 4; ++j) xoff[j] = (tr * 8) ^ (8 * j);

    unsigned long long acc[4][4];
    #pragma unroll
    for (int m = 0; m < 4; ++m)
        #pragma unroll
        for (int c = 0; c < 4; ++c) acc[m][c] = 0ull;

    // prologue: stage chunk 0
    float4 st[8];
    #pragma unroll
    for (int i = 0; i < 8; ++i) st[i] = *(const float4*)(xB + xoffb[i]);

    #pragma unroll 1
    for (int ch = 0; ch < NCH; ++ch) {
        // ---- store staged chunk, swizzled: phys_col = row ^ (4*tc) ----
        #pragma unroll
        for (int i = 0; i < 8; ++i) {
            int row = tr + 16 * i;
            int p   = row ^ (4 * tc);
            xs[(tc * 4 + 0) * TM + p] = st[i].x;
            xs[(tc * 4 + 1) * TM + p] = st[i].y;
            xs[(tc * 4 + 2) * TM + p] = st[i].z;
            xs[(tc * 4 + 3) * TM + p] = st[i].w;
        }
        __syncthreads();

        // ---- prefetch next chunk (overlaps compute) ----
        if (ch + 1 < NCH) {
            #pragma unroll
            for (int i = 0; i < 8; ++i)
                st[i] = *(const float4*)(xB + xoffb[i] + (ch + 1) * (KC * 4));
        }

        const float* wk = w1s + tc * 4 + ch * KC * HBLK;
        #pragma unroll
        for (int k = 0; k < KC; ++k) {
            const float* xb = &xs[xoff[(k >> 3) & 3] + k * TM];
            ulonglong2 xa = *(const ulonglong2*)(xb + (k & 4));          // rows 0..3
            ulonglong2 xv = *(const ulonglong2*)(xb + ((k & 4) ^ 4));    // rows 4..7
            float4 wv = *(const float4*)(wk + k * HBLK);
            unsigned long long xq[4] = { xa.x, xa.y, xv.x, xv.y };
            unsigned long long w0 = pack2(wv.x), w1 = pack2(wv.y),
                               w2 = pack2(wv.z), w3 = pack2(wv.w);
            #pragma unroll
            for (int m = 0; m < 4; ++m) {
                fma2(acc[m][0], xq[m], w0);
                fma2(acc[m][1], xq[m], w1);
                fma2(acc[m][2], xq[m], w2);
                fma2(acc[m][3], xq[m], w3);
            }
        }
        __syncthreads();
    }

    // ---- epilogue: silu (scale already folded), W2 (1/sqrt(128) folded) ----
    float4 w2v[4];
    #pragma unroll
    for (int c = 0; c < 4; ++c) {
        float4 t = *(const float4*)&W2[(hd * HBLK + tc * 4 + c) * DOUT];
        w2v[c] = make_float4(t.x * 0.08838834764831845f, t.y * 0.08838834764831845f,
                             t.z * 0.08838834764831845f, t.w * 0.08838834764831845f);
    }

    float v[8][DOUT];
    #pragma unroll
    for (int r = 0; r < 8; ++r)
        #pragma unroll
        for (int d = 0; d < DOUT; ++d) v[r][d] = 0.f;

    #pragma unroll
    for (int m = 0; m < 4; ++m) {
        #pragma unroll
        for (int c = 0; c < 4; ++c) {
            float lo, hi;
            unpack2(acc[m][c], lo, hi);
            float slo = lo / (1.f + __expf(-lo));
            float shi = hi / (1.f + __expf(-hi));
            v[2 * m][0]     += slo * w2v[c].x;  v[2 * m][1]     += slo * w2v[c].y;
            v[2 * m][2]     += slo * w2v[c].z;  v[2 * m][3]     += slo * w2v[c].w;
            v[2 * m + 1][0] += shi * w2v[c].x;  v[2 * m + 1][1] += shi * w2v[c].y;
            v[2 * m + 1][2] += shi * w2v[c].z;  v[2 * m + 1][3] += shi * w2v[c].w;
        }
    }

    // ---- deterministic butterfly reduction over the 8 col-group lanes ----
    // lanes sharing tr are contiguous (tid = tr*8 + tc); masks 1,2,4 stay in-group
    #pragma unroll
    for (int mbit = 1; mbit <= 4; mbit <<= 1)
        #pragma unroll
        for (int r = 0; r < 8; ++r)
            #pragma unroll
            for (int d = 0; d < DOUT; ++d)
                v[r][d] += __shfl_xor_sync(0xffffffffu, v[r][d], mbit);

    // ---- lane tc owns row tr*8 + tc: scattered float4 store ----
    const int myrow = start + tr * 8 + tc;
    if (myrow < cnt) {
        float4 o = make_float4(0.f, 0.f, 0.f, 0.f);
        #pragma unroll
        for (int r = 0; r < 8; ++r)
            if (tc == r) o = make_float4(v[r][0], v[r][1], v[r][2], v[r][3]);
        int ridx = g_idx[hd][myrow];
        *(float4*)(out + (size_t)ridx * DOUT) = o;
    }
}

// ---------------- launch ----------------
extern "C" void kernel_launch(void* const* d_in, const int* in_sizes, int n_in,
                              void* d_out, int out_size) {
    const float* x     = (const float*)d_in[0];
    const float* W1    = (const float*)d_in[1];
    const float* W2    = (const float*)d_in[2];
    const int*   heads = (const int*)d_in[3];
    int n = in_sizes[3];

    zero_kernel<<<1, 32>>>();
    scatter_kernel<<<(n + 255) / 256, 256>>>(heads, n);

    // worst case sum of per-head ceils
    int nt = (n + TM - 1) / TM + (NHEAD - 1);
    gemm_kernel<<<nt, 128>>>(x, W1, W2, (float*)d_out);
}